// round 11
// baseline (speedup 1.0000x reference)
#include <cuda_runtime.h>
#include <math.h>

#define Nn 50000
#define Ee 1600000
#define Ff 128
#define Ll 3
#define Gg 128
#define Cc 10
#define BN_EPS 1e-5f

#define TILE_M 64
#define FUSED_THREADS 512
#define FUSED_GRID 148
#define NTILES ((Nn + TILE_M - 1) / TILE_M)            // 782
#define FUSED_SMEM ((2*128*128 + 2*TILE_M*128) * 4)    // 196608 B

// scratch (device globals — no allocation allowed)
__device__ __align__(256) float g_x1[(size_t)Nn * Ff];
__device__ __align__(256) float g_x2[(size_t)Nn * Ff];
__device__ __align__(256) float g_pool[Gg * Ff];
__device__ __align__(256) float g_cnt[Gg];
// CSR scratch
__device__ __align__(256) int g_deg[Nn];
__device__ __align__(256) int g_rowptr[Nn + 1];
__device__ __align__(256) int g_cursor[Nn];
__device__ __align__(256) int g_srcs[Ee];

// ---- tf32 helpers ----
__device__ __forceinline__ unsigned f2tf32(float f) {
    unsigned r;
    asm("cvt.rna.tf32.f32 %0, %1;" : "=r"(r) : "f"(f));
    return r;
}
__device__ __forceinline__ void mma_tf32(float& d0, float& d1, float& d2, float& d3,
                                         unsigned a0, unsigned a1, unsigned a2, unsigned a3,
                                         unsigned b0, unsigned b1) {
    asm("mma.sync.aligned.m16n8k8.row.col.f32.tf32.tf32.f32 "
        "{%0,%1,%2,%3},{%4,%5,%6,%7},{%8,%9},{%0,%1,%2,%3};"
        : "+f"(d0), "+f"(d1), "+f"(d2), "+f"(d3)
        : "r"(a0), "r"(a1), "r"(a2), "r"(a3), "r"(b0), "r"(b1));
}

// ---- cp.async helpers ----
__device__ __forceinline__ unsigned smem_u32(const void* p) {
    return (unsigned)__cvta_generic_to_shared(p);
}
__device__ __forceinline__ void cpa16(unsigned dst, const void* src, bool pred) {
    int sz = pred ? 16 : 0;
    asm volatile("cp.async.cg.shared.global [%0], [%1], 16, %2;"
                 :: "r"(dst), "l"(src), "r"(sz) : "memory");
}
__device__ __forceinline__ void cpa_commit() {
    asm volatile("cp.async.commit_group;" ::: "memory");
}

// ---------------------------------------------------------------------------
__global__ void zero_deg_kernel(int* __restrict__ deg) {
    int i = blockIdx.x * blockDim.x + threadIdx.x;
    if (i < Nn) deg[i] = 0;
}

// degree histogram, 4 edges/thread (int4)
__global__ void count_kernel(const int* __restrict__ ei, int* __restrict__ deg) {
    int i = blockIdx.x * blockDim.x + threadIdx.x;
    if (i < Ee / 4) {
        int4 d = ((const int4*)(ei + Ee))[i];
        atomicAdd(&deg[d.x], 1);
        atomicAdd(&deg[d.y], 1);
        atomicAdd(&deg[d.z], 1);
        atomicAdd(&deg[d.w], 1);
    }
}

// single-block exclusive scan over deg -> rowptr, cursor
__global__ void scan_kernel(const int* __restrict__ deg,
                            int* __restrict__ rowptr, int* __restrict__ cursor) {
    __shared__ int wsum[32];
    __shared__ int s_carry;
    int t = threadIdx.x;              // 1024 threads
    int lane = t & 31, wid = t >> 5;
    if (t == 0) s_carry = 0;
    __syncthreads();
    for (int base = 0; base < Nn; base += 1024) {
        int idx = base + t;
        int v = (idx < Nn) ? deg[idx] : 0;
        int inc = v;
        #pragma unroll
        for (int d = 1; d < 32; d <<= 1) {
            int o = __shfl_up_sync(0xffffffffu, inc, d);
            if (lane >= d) inc += o;
        }
        if (lane == 31) wsum[wid] = inc;
        __syncthreads();
        if (wid == 0) {
            int wv = wsum[lane];
            int winc = wv;
            #pragma unroll
            for (int d = 1; d < 32; d <<= 1) {
                int o = __shfl_up_sync(0xffffffffu, winc, d);
                if (lane >= d) winc += o;
            }
            wsum[lane] = winc - wv;
        }
        __syncthreads();
        int excl = s_carry + wsum[wid] + inc - v;
        if (idx < Nn) { rowptr[idx] = excl; cursor[idx] = excl; }
        __syncthreads();
        if (t == 1023) s_carry += wsum[31] + inc;
        __syncthreads();
    }
    if (t == 0) rowptr[Nn] = s_carry;
}

// CSR fill, 4 edges/thread (int4)
__global__ void fill_kernel(const int* __restrict__ ei,
                            int* __restrict__ cursor, int* __restrict__ srcs) {
    int i = blockIdx.x * blockDim.x + threadIdx.x;
    if (i < Ee / 4) {
        int4 s = ((const int4*)ei)[i];
        int4 d = ((const int4*)(ei + Ee))[i];
        srcs[atomicAdd(&cursor[d.x], 1)] = s.x;
        srcs[atomicAdd(&cursor[d.y], 1)] = s.y;
        srcs[atomicAdd(&cursor[d.z], 1)] = s.z;
        srcs[atomicAdd(&cursor[d.w], 1)] = s.w;
    }
}

// ---------------------------------------------------------------------------
// Fused persistent GIN layer: warp-specialized producer/consumer.
//   warps 8..15: gather tiles (64 nodes) into swizzled SMEM (double-buffered)
//   warps 0..7 : tf32 MMA x2 + bias/ReLU/BN epilogue
// Named barriers: 1+p = full[p], 3+p = empty[p] (512), 5 = consumer-only (256).
__global__ __launch_bounds__(FUSED_THREADS, 1)
void layer_kernel(const float* __restrict__ x,
                  const int* __restrict__ rowptr, const int* __restrict__ srcs,
                  const float* __restrict__ W1, const float* __restrict__ b1g,
                  const float* __restrict__ W2, const float* __restrict__ b2g,
                  const float* __restrict__ gamma, const float* __restrict__ beta,
                  const float* __restrict__ rmean, const float* __restrict__ rvar,
                  float* __restrict__ xout) {
    extern __shared__ float sm[];
    float* sW1 = sm;                        // 16384 floats
    float* sW2 = sm + 16384;                // 16384 floats
    float* sT0 = sm + 32768;                // 8192 floats
    float* sT1 = sm + 40960;                // 8192 floats

    int t = threadIdx.x;
    int lane = t & 31;
    int warp = t >> 5;
    unsigned base = smem_u32(sm);

    // stage weights once, swizzled: float4-chunk n4 of k-row stored at n4^((k&3)<<1)
    for (int i = t; i < 4096; i += FUSED_THREADS) {
        int k = i >> 5, n4 = i & 31;
        int dchunk = (i & ~31) | (n4 ^ ((k & 3) << 1));
        cpa16(base + dchunk * 16,         (const float4*)W1 + i, true);
        cpa16(base + 65536 + dchunk * 16, (const float4*)W2 + i, true);
    }
    cpa_commit();
    asm volatile("cp.async.wait_group 0;" ::: "memory");
    __syncthreads();
    // round weights to tf32 (rna) in place
    for (int i = t; i < 8192; i += FUSED_THREADS) {
        float4 v = ((float4*)sm)[i];
        v.x = __uint_as_float(f2tf32(v.x));
        v.y = __uint_as_float(f2tf32(v.y));
        v.z = __uint_as_float(f2tf32(v.z));
        v.w = __uint_as_float(f2tf32(v.w));
        ((float4*)sm)[i] = v;
    }
    __syncthreads();

    if (warp >= 8) {
        // ================= PRODUCER =================
        int pw = warp - 8;          // 0..7 -> rows pw*8 .. pw*8+7 of each tile
        const float* xb = x + lane * 4;
        int p = 0, it = 0;
        for (int tile = blockIdx.x; tile < NTILES; tile += FUSED_GRID, p ^= 1, it++) {
            if (it >= 2)
                asm volatile("bar.sync %0, 512;" :: "r"(3 + p) : "memory");
            float* sH = p ? sT1 : sT0;
            int row0 = tile * TILE_M;
            #pragma unroll 1
            for (int r8 = 0; r8 < 8; r8++) {
                int row  = pw * 8 + r8;
                int node = row0 + row;
                float4 a0 = make_float4(0.f, 0.f, 0.f, 0.f);
                if (node < Nn) {
                    a0 = __ldg((const float4*)(xb + (size_t)node * Ff));
                    float4 a1 = make_float4(0.f, 0.f, 0.f, 0.f);
                    float4 a2 = make_float4(0.f, 0.f, 0.f, 0.f);
                    float4 a3 = make_float4(0.f, 0.f, 0.f, 0.f);
                    int beg = rowptr[node], end = rowptr[node + 1];
                    for (int e0 = beg; e0 < end; e0 += 32) {
                        int my = (e0 + lane < end) ? srcs[e0 + lane] : -1;
                        int cnt = min(end - e0, 32);
                        int j = 0;
                        #pragma unroll 2
                        for (; j + 4 <= cnt; j += 4) {
                            int s0 = __shfl_sync(0xffffffffu, my, j);
                            int s1 = __shfl_sync(0xffffffffu, my, j + 1);
                            int s2 = __shfl_sync(0xffffffffu, my, j + 2);
                            int s3 = __shfl_sync(0xffffffffu, my, j + 3);
                            float4 v0 = __ldg((const float4*)(xb + (size_t)s0 * Ff));
                            float4 v1 = __ldg((const float4*)(xb + (size_t)s1 * Ff));
                            float4 v2 = __ldg((const float4*)(xb + (size_t)s2 * Ff));
                            float4 v3 = __ldg((const float4*)(xb + (size_t)s3 * Ff));
                            a0.x += v0.x; a0.y += v0.y; a0.z += v0.z; a0.w += v0.w;
                            a1.x += v1.x; a1.y += v1.y; a1.z += v1.z; a1.w += v1.w;
                            a2.x += v2.x; a2.y += v2.y; a2.z += v2.z; a2.w += v2.w;
                            a3.x += v3.x; a3.y += v3.y; a3.z += v3.z; a3.w += v3.w;
                        }
                        for (; j < cnt; j++) {
                            int s0 = __shfl_sync(0xffffffffu, my, j);
                            float4 v0 = __ldg((const float4*)(xb + (size_t)s0 * Ff));
                            a0.x += v0.x; a0.y += v0.y; a0.z += v0.z; a0.w += v0.w;
                        }
                    }
                    a0.x += a1.x + a2.x + a3.x;
                    a0.y += a1.y + a2.y + a3.y;
                    a0.z += a1.z + a2.z + a3.z;
                    a0.w += a1.w + a2.w + a3.w;
                    a0.x = __uint_as_float(f2tf32(a0.x));
                    a0.y = __uint_as_float(f2tf32(a0.y));
                    a0.z = __uint_as_float(f2tf32(a0.z));
                    a0.w = __uint_as_float(f2tf32(a0.w));
                }
                // swizzled STS: float4-chunk (lane) of row stored at lane^(row&7)
                int chunk = row * 32 + (lane ^ (row & 7));
                *(float4*)(sH + chunk * 4) = a0;
            }
            asm volatile("bar.arrive %0, 512;" :: "r"(1 + p) : "memory");
        }
    } else {
        // ================= CONSUMER =================
        int wm = warp & 3;         // rows wm*16..+16
        int wn = warp >> 2;        // cols wn*64..+64 (8 n8-blocks)
        int ar  = wm * 16 + (lane >> 2);
        int acl = lane & 3;
        int s1  = (lane >> 2) << 2;
        int arO  = ar * 128;
        int arO8 = arO + 1024;
        int kl = lane & 3;
        int cidx[8];
        #pragma unroll
        for (int j = 0; j < 8; j++)
            cidx[j] = (wn * 64 + j * 8 + (lane >> 2)) ^ (kl << 3);

        const unsigned* sW1u = (const unsigned*)sW1;
        const unsigned* sW2u = (const unsigned*)sW2;

        int p = 0;
        for (int tile = blockIdx.x; tile < NTILES; tile += FUSED_GRID, p ^= 1) {
            asm volatile("bar.sync %0, 512;" :: "r"(1 + p) : "memory");
            float* sH = p ? sT1 : sT0;
            const unsigned* sHu = (const unsigned*)sH;
            int row0 = tile * TILE_M;

            float acc[8][4];
            #pragma unroll
            for (int j = 0; j < 8; j++)
                #pragma unroll
                for (int c = 0; c < 4; c++) acc[j][c] = 0.f;

            // ---- GEMM1 ----
            #pragma unroll
            for (int ks = 0; ks < 16; ks++) {
                int k0 = ks * 8;
                int c1 = (k0 | acl) ^ s1;
                unsigned a0 = sHu[arO + c1],       a1 = sHu[arO8 + c1];
                unsigned a2 = sHu[arO + (c1 ^ 4)], a3 = sHu[arO8 + (c1 ^ 4)];
                int krow = (k0 + kl) * 128;
                #pragma unroll
                for (int j = 0; j < 8; j++) {
                    unsigned b0 = sW1u[krow + cidx[j]];
                    unsigned b1 = sW1u[krow + 512 + cidx[j]];
                    mma_tf32(acc[j][0], acc[j][1], acc[j][2], acc[j][3],
                             a0, a1, a2, a3, b0, b1);
                }
            }
            asm volatile("bar.sync 5, 256;" ::: "memory");   // all A reads done
            #pragma unroll
            for (int j = 0; j < 8; j++) {
                int c = wn * 64 + j * 8 + 2 * (lane & 3);
                float2 bb = *(const float2*)(b1g + c);
                unsigned v0 = f2tf32(fmaxf(acc[j][0] + bb.x, 0.f));
                unsigned v1 = f2tf32(fmaxf(acc[j][1] + bb.y, 0.f));
                unsigned v2 = f2tf32(fmaxf(acc[j][2] + bb.x, 0.f));
                unsigned v3 = f2tf32(fmaxf(acc[j][3] + bb.y, 0.f));
                int o = arO + (c ^ s1);
                ((uint2*)sH)[o >> 1]          = make_uint2(v0, v1);
                ((uint2*)sH)[(o + 1024) >> 1] = make_uint2(v2, v3);
            }
            asm volatile("bar.sync 5, 256;" ::: "memory");   // writes visible

            // ---- GEMM2 ----
            #pragma unroll
            for (int j = 0; j < 8; j++)
                #pragma unroll
                for (int c = 0; c < 4; c++) acc[j][c] = 0.f;
            #pragma unroll
            for (int ks = 0; ks < 16; ks++) {
                int k0 = ks * 8;
                int c1 = (k0 | acl) ^ s1;
                unsigned a0 = sHu[arO + c1],       a1 = sHu[arO8 + c1];
                unsigned a2 = sHu[arO + (c1 ^ 4)], a3 = sHu[arO8 + (c1 ^ 4)];
                int krow = (k0 + kl) * 128;
                #pragma unroll
                for (int j = 0; j < 8; j++) {
                    unsigned b0 = sW2u[krow + cidx[j]];
                    unsigned b1 = sW2u[krow + 512 + cidx[j]];
                    mma_tf32(acc[j][0], acc[j][1], acc[j][2], acc[j][3],
                             a0, a1, a2, a3, b0, b1);
                }
            }
            // ---- BN + ReLU epilogue ----
            {
                int r0 = row0 + ar;
                int r8 = r0 + 8;
                #pragma unroll
                for (int j = 0; j < 8; j++) {
                    int c = wn * 64 + j * 8 + 2 * (lane & 3);
                    float2 b2v = *(const float2*)(b2g + c);
                    float2 gm  = *(const float2*)(gamma + c);
                    float2 bt  = *(const float2*)(beta + c);
                    float2 rm  = *(const float2*)(rmean + c);
                    float2 rv  = *(const float2*)(rvar + c);
                    float sx = gm.x * rsqrtf(rv.x + BN_EPS);
                    float sy = gm.y * rsqrtf(rv.y + BN_EPS);
                    float ox = bt.x + (b2v.x - rm.x) * sx;
                    float oy = bt.y + (b2v.y - rm.y) * sy;
                    if (r0 < Nn) {
                        float2 v;
                        v.x = fmaxf(fmaf(acc[j][0], sx, ox), 0.f);
                        v.y = fmaxf(fmaf(acc[j][1], sy, oy), 0.f);
                        *(float2*)(xout + (size_t)r0 * 128 + c) = v;
                    }
                    if (r8 < Nn) {
                        float2 v;
                        v.x = fmaxf(fmaf(acc[j][2], sx, ox), 0.f);
                        v.y = fmaxf(fmaf(acc[j][3], sy, oy), 0.f);
                        *(float2*)(xout + (size_t)r8 * 128 + c) = v;
                    }
                }
            }
            asm volatile("bar.arrive %0, 512;" :: "r"(3 + p) : "memory");
        }
    }
}

// ---------------------------------------------------------------------------
__global__ void zero_pool_kernel(float* __restrict__ pool, float* __restrict__ cnt) {
    int i = blockIdx.x * blockDim.x + threadIdx.x;
    if (i < Gg * Ff) pool[i] = 0.f;
    if (i < Gg) cnt[i] = 0.f;
}

__global__ void pool_kernel(const float* __restrict__ x,
                            const int* __restrict__ batch,
                            float* __restrict__ pool, float* __restrict__ cnt) {
    int gid  = blockIdx.x * blockDim.x + threadIdx.x;
    int node = gid >> 5;
    int lane = gid & 31;
    if (node >= Nn) return;
    int g = batch[node];
    float4 v = *(const float4*)(x + (size_t)node * Ff + lane * 4);
    float* p = pool + g * Ff + lane * 4;
    asm volatile("red.global.add.v4.f32 [%0], {%1,%2,%3,%4};"
                 :: "l"(p), "f"(v.x), "f"(v.y), "f"(v.z), "f"(v.w) : "memory");
    if (lane == 0) atomicAdd(&cnt[g], 1.0f);
}

// ---------------------------------------------------------------------------
__global__ void final_kernel(const float* __restrict__ pool, const float* __restrict__ cnt,
                             const float* __restrict__ fc_w, const float* __restrict__ fc_b,
                             float* __restrict__ out) {
    int g = threadIdx.x;
    if (g >= Gg) return;
    float inv = 1.0f / fmaxf(cnt[g], 1.0f);
    float logits[Cc];
    #pragma unroll
    for (int j = 0; j < Cc; j++) logits[j] = fc_b[j];
    for (int k = 0; k < Ff; k++) {
        float p = pool[g * Ff + k] * inv;
        #pragma unroll
        for (int j = 0; j < Cc; j++) logits[j] += p * fc_w[k * Cc + j];
    }
    float m = logits[0];
    #pragma unroll
    for (int j = 1; j < Cc; j++) m = fmaxf(m, logits[j]);
    float s = 0.f;
    #pragma unroll
    for (int j = 0; j < Cc; j++) s += expf(logits[j] - m);
    float ls = logf(s) + m;
    #pragma unroll
    for (int j = 0; j < Cc; j++) out[g * Cc + j] = logits[j] - ls;
}

// ---------------------------------------------------------------------------
extern "C" void kernel_launch(void* const* d_in, const int* in_sizes, int n_in,
                              void* d_out, int out_size) {
    const float* x     = (const float*)d_in[0];
    const int*   ei    = (const int*)d_in[1];
    const int*   batch = (const int*)d_in[2];
    const float* W1    = (const float*)d_in[3];
    const float* b1    = (const float*)d_in[4];
    const float* W2    = (const float*)d_in[5];
    const float* b2    = (const float*)d_in[6];
    const float* gamma = (const float*)d_in[7];
    const float* beta  = (const float*)d_in[8];
    const float* rmean = (const float*)d_in[9];
    const float* rvar  = (const float*)d_in[10];
    const float* fc_w  = (const float*)d_in[11];
    const float* fc_b  = (const float*)d_in[12];
    float* out = (float*)d_out;

    cudaFuncSetAttribute(layer_kernel, cudaFuncAttributeMaxDynamicSharedMemorySize, FUSED_SMEM);

    float *x1, *x2, *pool, *cnt;
    int *deg, *rowptr, *cursor, *srcs;
    cudaGetSymbolAddress((void**)&x1,     g_x1);
    cudaGetSymbolAddress((void**)&x2,     g_x2);
    cudaGetSymbolAddress((void**)&pool,   g_pool);
    cudaGetSymbolAddress((void**)&cnt,    g_cnt);
    cudaGetSymbolAddress((void**)&deg,    g_deg);
    cudaGetSymbolAddress((void**)&rowptr, g_rowptr);
    cudaGetSymbolAddress((void**)&cursor, g_cursor);
    cudaGetSymbolAddress((void**)&srcs,   g_srcs);

    const int pool_blocks = (Nn * 32 + 255) / 256;

    // build CSR (dst-sorted) once per launch
    zero_deg_kernel<<<(Nn + 255) / 256, 256>>>(deg);
    count_kernel<<<(Ee / 4 + 255) / 256, 256>>>(ei, deg);
    scan_kernel<<<1, 1024>>>(deg, rowptr, cursor);
    fill_kernel<<<(Ee / 4 + 255) / 256, 256>>>(ei, cursor, srcs);

    const float* cur = x;
    float* outs[Ll] = { x1, x2, x1 };
    for (int l = 0; l < Ll; l++) {
        layer_kernel<<<FUSED_GRID, FUSED_THREADS, FUSED_SMEM>>>(
            cur, rowptr, srcs,
            W1 + (size_t)l * 128 * 128, b1 + (size_t)l * 128,
            W2 + (size_t)l * 128 * 128, b2 + (size_t)l * 128,
            gamma + (size_t)l * 128, beta + (size_t)l * 128,
            rmean + (size_t)l * 128, rvar + (size_t)l * 128,
            outs[l]);
        cur = outs[l];
    }

    zero_pool_kernel<<<(Gg * Ff + 255) / 256, 256>>>(pool, cnt);
    pool_kernel<<<pool_blocks, 256>>>(cur, batch, pool, cnt);
    final_kernel<<<1, 128>>>(pool, cnt, fc_w, fc_b, out);
}

// round 12
// speedup vs baseline: 1.6935x; 1.6935x over previous
#include <cuda_runtime.h>
#include <math.h>

#define Nn 50000
#define Ee 1600000
#define Ff 128
#define Ll 3
#define Gg 128
#define Cc 10
#define BN_EPS 1e-5f

#define TILE_M 64
#define MLP_THREADS 512
#define MLP_GRID 148
#define NTILES ((Nn + TILE_M - 1) / TILE_M)          // 782
#define MLP_SMEM ((2*128*128 + 2*TILE_M*128) * 4)    // 196608 B
#define PAD 128                                       // padded CSR row length

// scratch (device globals — no allocation allowed)
__device__ __align__(256) float g_agg[(size_t)Nn * Ff];
__device__ __align__(256) float g_x1[(size_t)Nn * Ff];
__device__ __align__(256) float g_x2[(size_t)Nn * Ff];
__device__ __align__(256) float g_pool[Gg * Ff];
__device__ __align__(256) float g_cnt[Gg];
// padded CSR scratch: deg doubles as fill-cursor and row length
__device__ __align__(256) int g_deg[Nn];
__device__ __align__(256) int g_srcs[(size_t)Nn * PAD];

// ---- tf32 helpers ----
__device__ __forceinline__ unsigned f2tf32(float f) {
    unsigned r;
    asm("cvt.rna.tf32.f32 %0, %1;" : "=r"(r) : "f"(f));
    return r;
}
__device__ __forceinline__ void mma_tf32(float& d0, float& d1, float& d2, float& d3,
                                         unsigned a0, unsigned a1, unsigned a2, unsigned a3,
                                         unsigned b0, unsigned b1) {
    asm("mma.sync.aligned.m16n8k8.row.col.f32.tf32.tf32.f32 "
        "{%0,%1,%2,%3},{%4,%5,%6,%7},{%8,%9},{%0,%1,%2,%3};"
        : "+f"(d0), "+f"(d1), "+f"(d2), "+f"(d3)
        : "r"(a0), "r"(a1), "r"(a2), "r"(a3), "r"(b0), "r"(b1));
}

// ---- cp.async helpers ----
__device__ __forceinline__ unsigned smem_u32(const void* p) {
    return (unsigned)__cvta_generic_to_shared(p);
}
__device__ __forceinline__ void cpa16(unsigned dst, const void* src, bool pred) {
    int sz = pred ? 16 : 0;
    asm volatile("cp.async.cg.shared.global [%0], [%1], 16, %2;"
                 :: "r"(dst), "l"(src), "r"(sz) : "memory");
}
__device__ __forceinline__ void cpa_commit() {
    asm volatile("cp.async.commit_group;" ::: "memory");
}

// ---------------------------------------------------------------------------
// one kernel zeroes deg + pool + cnt
__global__ void zero_kernel(int* __restrict__ deg, float* __restrict__ pool,
                            float* __restrict__ cnt) {
    int i = blockIdx.x * blockDim.x + threadIdx.x;
    if (i < Nn) deg[i] = 0;
    if (i < Gg * Ff) pool[i] = 0.f;
    if (i < Gg) cnt[i] = 0.f;
}

// single-pass padded CSR fill, 4 edges/thread (int4)
__global__ void fill_kernel(const int* __restrict__ ei,
                            int* __restrict__ deg, int* __restrict__ srcs) {
    int i = blockIdx.x * blockDim.x + threadIdx.x;
    if (i < Ee / 4) {
        int4 s = ((const int4*)ei)[i];
        int4 d = ((const int4*)(ei + Ee))[i];
        int c0 = atomicAdd(&deg[d.x], 1);
        int c1 = atomicAdd(&deg[d.y], 1);
        int c2 = atomicAdd(&deg[d.z], 1);
        int c3 = atomicAdd(&deg[d.w], 1);
        srcs[(d.x << 7) + c0] = s.x;
        srcs[(d.y << 7) + c1] = s.y;
        srcs[(d.z << 7) + c2] = s.z;
        srcs[(d.w << 7) + c3] = s.w;
    }
}

// ---------------------------------------------------------------------------
// one warp per node: agg[node] = x[node] + sum_{s in in(node)} x[s]
// result rounded to tf32 (rna) — agg only feeds the tensor-core MLP.
__global__ void gather_kernel(const float* __restrict__ x,
                              const int* __restrict__ deg,
                              const int* __restrict__ srcs,
                              float* __restrict__ agg) {
    int gid  = blockIdx.x * blockDim.x + threadIdx.x;
    int node = gid >> 5;
    int lane = gid & 31;
    if (node >= Nn) return;
    int beg = node << 7;
    int end = beg + deg[node];
    const float* xb = x + lane * 4;
    float4 a0 = __ldg((const float4*)(xb + (size_t)node * Ff));
    float4 a1 = make_float4(0.f, 0.f, 0.f, 0.f);
    float4 a2 = make_float4(0.f, 0.f, 0.f, 0.f);
    float4 a3 = make_float4(0.f, 0.f, 0.f, 0.f);
    for (int e0 = beg; e0 < end; e0 += 32) {
        int my = (e0 + lane < end) ? srcs[e0 + lane] : -1;
        int cnt = min(end - e0, 32);
        int j = 0;
        #pragma unroll 2
        for (; j + 4 <= cnt; j += 4) {
            int s0 = __shfl_sync(0xffffffffu, my, j);
            int s1 = __shfl_sync(0xffffffffu, my, j + 1);
            int s2 = __shfl_sync(0xffffffffu, my, j + 2);
            int s3 = __shfl_sync(0xffffffffu, my, j + 3);
            float4 v0 = __ldg((const float4*)(xb + (size_t)s0 * Ff));
            float4 v1 = __ldg((const float4*)(xb + (size_t)s1 * Ff));
            float4 v2 = __ldg((const float4*)(xb + (size_t)s2 * Ff));
            float4 v3 = __ldg((const float4*)(xb + (size_t)s3 * Ff));
            a0.x += v0.x; a0.y += v0.y; a0.z += v0.z; a0.w += v0.w;
            a1.x += v1.x; a1.y += v1.y; a1.z += v1.z; a1.w += v1.w;
            a2.x += v2.x; a2.y += v2.y; a2.z += v2.z; a2.w += v2.w;
            a3.x += v3.x; a3.y += v3.y; a3.z += v3.z; a3.w += v3.w;
        }
        for (; j < cnt; j++) {
            int s0 = __shfl_sync(0xffffffffu, my, j);
            float4 v0 = __ldg((const float4*)(xb + (size_t)s0 * Ff));
            a0.x += v0.x; a0.y += v0.y; a0.z += v0.z; a0.w += v0.w;
        }
    }
    a0.x += a1.x + a2.x + a3.x;
    a0.y += a1.y + a2.y + a3.y;
    a0.z += a1.z + a2.z + a3.z;
    a0.w += a1.w + a2.w + a3.w;
    a0.x = __uint_as_float(f2tf32(a0.x));
    a0.y = __uint_as_float(f2tf32(a0.y));
    a0.z = __uint_as_float(f2tf32(a0.z));
    a0.w = __uint_as_float(f2tf32(a0.w));
    *(float4*)(agg + (size_t)node * Ff + lane * 4) = a0;
}

// ---------------------------------------------------------------------------
// Persistent tensor-core MLP (tf32 mma.sync.m16n8k8).
// Weights staged once + rounded to tf32 in SMEM; tiles double-buffered cp.async.
__global__ __launch_bounds__(MLP_THREADS, 1)
void mlp_kernel(const float* __restrict__ agg,
                const float* __restrict__ W1, const float* __restrict__ b1g,
                const float* __restrict__ W2, const float* __restrict__ b2g,
                const float* __restrict__ gamma, const float* __restrict__ beta,
                const float* __restrict__ rmean, const float* __restrict__ rvar,
                float* __restrict__ xout) {
    extern __shared__ float sm[];
    float* sW1 = sm;                        // 16384 floats
    float* sW2 = sm + 16384;                // 16384 floats
    float* sT0 = sm + 32768;                // 8192 floats (tile buf 0)
    float* sT1 = sm + 32768 + 8192;         // 8192 floats (tile buf 1)

    int t = threadIdx.x;
    int lane = t & 31;
    int warp = t >> 5;
    int wm = warp & 3;        // m-group: rows wm*16 .. +16
    int wn = warp >> 2;       // n-group: cols wn*32 .. +32
    unsigned base = smem_u32(sm);

    // ---- stage weights once, swizzled ----
    for (int i = t; i < 4096; i += MLP_THREADS) {
        int k = i >> 5, n4 = i & 31;
        int dchunk = (i & ~31) | (n4 ^ ((k & 3) << 1));
        cpa16(base + dchunk * 16,         (const float4*)W1 + i, true);
        cpa16(base + 65536 + dchunk * 16, (const float4*)W2 + i, true);
    }
    cpa_commit();

    // ---- prefetch first tile into buf 0, swizzled ----
    {
        int row0 = blockIdx.x * TILE_M;
        const float4* src = (const float4*)agg + (size_t)row0 * 32;
        unsigned dst = base + 131072;
        for (int i = t; i < 2048; i += MLP_THREADS) {
            int row = i >> 5, c4 = i & 31;
            int dchunk = (i & ~31) | (c4 ^ (row & 7));
            bool ok = (row0 + row) < Nn;
            cpa16(dst + dchunk * 16, ok ? (src + i) : (const float4*)agg, ok);
        }
        cpa_commit();
    }

    // wait for weights, round them to tf32 in place
    asm volatile("cp.async.wait_group 1;" ::: "memory");
    __syncthreads();
    for (int i = t; i < 8192; i += MLP_THREADS) {
        float4 v = ((float4*)sm)[i];
        v.x = __uint_as_float(f2tf32(v.x));
        v.y = __uint_as_float(f2tf32(v.y));
        v.z = __uint_as_float(f2tf32(v.z));
        v.w = __uint_as_float(f2tf32(v.w));
        ((float4*)sm)[i] = v;
    }
    __syncthreads();

    // ---- per-thread fragment geometry ----
    int ar  = wm * 16 + (lane >> 2);
    int acl = lane & 3;
    int s1  = (lane >> 2) << 2;
    int arO  = ar * 128;
    int arO8 = arO + 1024;
    int kl = lane & 3;
    int cidx[4];
    #pragma unroll
    for (int j = 0; j < 4; j++)
        cidx[j] = (wn * 32 + j * 8 + (lane >> 2)) ^ (kl << 3);

    // ---- hoisted epilogue params ----
    float2 bias1[4], scl[4], off[4];
    #pragma unroll
    for (int j = 0; j < 4; j++) {
        int c = wn * 32 + j * 8 + 2 * (lane & 3);
        bias1[j] = *(const float2*)(b1g + c);
        float2 b2v = *(const float2*)(b2g + c);
        float2 gm  = *(const float2*)(gamma + c);
        float2 bt  = *(const float2*)(beta + c);
        float2 rm  = *(const float2*)(rmean + c);
        float2 rv  = *(const float2*)(rvar + c);
        scl[j].x = gm.x * rsqrtf(rv.x + BN_EPS);
        scl[j].y = gm.y * rsqrtf(rv.y + BN_EPS);
        off[j].x = bt.x - rm.x * scl[j].x + b2v.x * scl[j].x;
        off[j].y = bt.y - rm.y * scl[j].y + b2v.y * scl[j].y;
    }

    const unsigned* sW1u = (const unsigned*)sW1;
    const unsigned* sW2u = (const unsigned*)sW2;

    int p = 0;
    for (int tile = blockIdx.x; tile < NTILES; tile += MLP_GRID, p ^= 1) {
        int nxt = tile + MLP_GRID;
        if (nxt < NTILES) {
            int row0n = nxt * TILE_M;
            const float4* src = (const float4*)agg + (size_t)row0n * 32;
            unsigned dst = base + 131072 + (p ^ 1) * 32768;
            for (int i = t; i < 2048; i += MLP_THREADS) {
                int row = i >> 5, c4 = i & 31;
                int dchunk = (i & ~31) | (c4 ^ (row & 7));
                bool ok = (row0n + row) < Nn;
                cpa16(dst + dchunk * 16, ok ? (src + i) : (const float4*)agg, ok);
            }
            cpa_commit();
            asm volatile("cp.async.wait_group 1;" ::: "memory");
        } else {
            asm volatile("cp.async.wait_group 0;" ::: "memory");
        }
        __syncthreads();

        float* sH = p ? sT1 : sT0;
        const unsigned* sHu = (const unsigned*)sH;
        int row0 = tile * TILE_M;

        float acc[4][4];
        #pragma unroll
        for (int j = 0; j < 4; j++)
            #pragma unroll
            for (int c = 0; c < 4; c++) acc[j][c] = 0.f;

        // ---- GEMM1: M = relu(H @ W1 + b1) ----
        #pragma unroll
        for (int ks = 0; ks < 16; ks++) {
            int k0 = ks * 8;
            int c1 = (k0 | acl) ^ s1;
            unsigned a0 = sHu[arO + c1],        a1 = sHu[arO8 + c1];
            unsigned a2 = sHu[arO + (c1 ^ 4)],  a3 = sHu[arO8 + (c1 ^ 4)];
            int krow = (k0 + kl) * 128;
            #pragma unroll
            for (int j = 0; j < 4; j++) {
                unsigned b0 = sW1u[krow + cidx[j]];
                unsigned b1 = sW1u[krow + 512 + cidx[j]];
                mma_tf32(acc[j][0], acc[j][1], acc[j][2], acc[j][3],
                         a0, a1, a2, a3, b0, b1);
            }
        }
        __syncthreads();
        #pragma unroll
        for (int j = 0; j < 4; j++) {
            int c = wn * 32 + j * 8 + 2 * (lane & 3);
            unsigned v0 = f2tf32(fmaxf(acc[j][0] + bias1[j].x, 0.f));
            unsigned v1 = f2tf32(fmaxf(acc[j][1] + bias1[j].y, 0.f));
            unsigned v2 = f2tf32(fmaxf(acc[j][2] + bias1[j].x, 0.f));
            unsigned v3 = f2tf32(fmaxf(acc[j][3] + bias1[j].y, 0.f));
            int o = arO + (c ^ s1);
            ((uint2*)sH)[o >> 1]          = make_uint2(v0, v1);
            ((uint2*)sH)[(o + 1024) >> 1] = make_uint2(v2, v3);
        }
        __syncthreads();

        // ---- GEMM2 + BN + ReLU ----
        #pragma unroll
        for (int j = 0; j < 4; j++)
            #pragma unroll
            for (int c = 0; c < 4; c++) acc[j][c] = 0.f;

        #pragma unroll
        for (int ks = 0; ks < 16; ks++) {
            int k0 = ks * 8;
            int c1 = (k0 | acl) ^ s1;
            unsigned a0 = sHu[arO + c1],        a1 = sHu[arO8 + c1];
            unsigned a2 = sHu[arO + (c1 ^ 4)],  a3 = sHu[arO8 + (c1 ^ 4)];
            int krow = (k0 + kl) * 128;
            #pragma unroll
            for (int j = 0; j < 4; j++) {
                unsigned b0 = sW2u[krow + cidx[j]];
                unsigned b1 = sW2u[krow + 512 + cidx[j]];
                mma_tf32(acc[j][0], acc[j][1], acc[j][2], acc[j][3],
                         a0, a1, a2, a3, b0, b1);
            }
        }
        {
            int r0 = row0 + ar;
            int r8 = r0 + 8;
            #pragma unroll
            for (int j = 0; j < 4; j++) {
                int c = wn * 32 + j * 8 + 2 * (lane & 3);
                if (r0 < Nn) {
                    float2 v;
                    v.x = fmaxf(fmaf(acc[j][0], scl[j].x, off[j].x), 0.f);
                    v.y = fmaxf(fmaf(acc[j][1], scl[j].y, off[j].y), 0.f);
                    *(float2*)(xout + (size_t)r0 * 128 + c) = v;
                }
                if (r8 < Nn) {
                    float2 v;
                    v.x = fmaxf(fmaf(acc[j][2], scl[j].x, off[j].x), 0.f);
                    v.y = fmaxf(fmaf(acc[j][3], scl[j].y, off[j].y), 0.f);
                    *(float2*)(xout + (size_t)r8 * 128 + c) = v;
                }
            }
        }
        __syncthreads();
    }
}

// ---------------------------------------------------------------------------
__global__ void pool_kernel(const float* __restrict__ x,
                            const int* __restrict__ batch,
                            float* __restrict__ pool, float* __restrict__ cnt) {
    int gid  = blockIdx.x * blockDim.x + threadIdx.x;
    int node = gid >> 5;
    int lane = gid & 31;
    if (node >= Nn) return;
    int g = batch[node];
    float4 v = *(const float4*)(x + (size_t)node * Ff + lane * 4);
    float* p = pool + g * Ff + lane * 4;
    asm volatile("red.global.add.v4.f32 [%0], {%1,%2,%3,%4};"
                 :: "l"(p), "f"(v.x), "f"(v.y), "f"(v.z), "f"(v.w) : "memory");
    if (lane == 0) atomicAdd(&cnt[g], 1.0f);
}

// ---------------------------------------------------------------------------
__global__ void final_kernel(const float* __restrict__ pool, const float* __restrict__ cnt,
                             const float* __restrict__ fc_w, const float* __restrict__ fc_b,
                             float* __restrict__ out) {
    int g = threadIdx.x;
    if (g >= Gg) return;
    float inv = 1.0f / fmaxf(cnt[g], 1.0f);
    float logits[Cc];
    #pragma unroll
    for (int j = 0; j < Cc; j++) logits[j] = fc_b[j];
    for (int k = 0; k < Ff; k++) {
        float p = pool[g * Ff + k] * inv;
        #pragma unroll
        for (int j = 0; j < Cc; j++) logits[j] += p * fc_w[k * Cc + j];
    }
    float m = logits[0];
    #pragma unroll
    for (int j = 1; j < Cc; j++) m = fmaxf(m, logits[j]);
    float s = 0.f;
    #pragma unroll
    for (int j = 0; j < Cc; j++) s += expf(logits[j] - m);
    float ls = logf(s) + m;
    #pragma unroll
    for (int j = 0; j < Cc; j++) out[g * Cc + j] = logits[j] - ls;
}

// ---------------------------------------------------------------------------
extern "C" void kernel_launch(void* const* d_in, const int* in_sizes, int n_in,
                              void* d_out, int out_size) {
    const float* x     = (const float*)d_in[0];
    const int*   ei    = (const int*)d_in[1];
    const int*   batch = (const int*)d_in[2];
    const float* W1    = (const float*)d_in[3];
    const float* b1    = (const float*)d_in[4];
    const float* W2    = (const float*)d_in[5];
    const float* b2    = (const float*)d_in[6];
    const float* gamma = (const float*)d_in[7];
    const float* beta  = (const float*)d_in[8];
    const float* rmean = (const float*)d_in[9];
    const float* rvar  = (const float*)d_in[10];
    const float* fc_w  = (const float*)d_in[11];
    const float* fc_b  = (const float*)d_in[12];
    float* out = (float*)d_out;

    cudaFuncSetAttribute(mlp_kernel, cudaFuncAttributeMaxDynamicSharedMemorySize, MLP_SMEM);

    float *agg, *x1, *x2, *pool, *cnt;
    int *deg, *srcs;
    cudaGetSymbolAddress((void**)&agg,  g_agg);
    cudaGetSymbolAddress((void**)&x1,   g_x1);
    cudaGetSymbolAddress((void**)&x2,   g_x2);
    cudaGetSymbolAddress((void**)&pool, g_pool);
    cudaGetSymbolAddress((void**)&cnt,  g_cnt);
    cudaGetSymbolAddress((void**)&deg,  g_deg);
    cudaGetSymbolAddress((void**)&srcs, g_srcs);

    const int gather_blocks = (Nn * 32 + 255) / 256;
    const int pool_blocks   = (Nn * 32 + 255) / 256;

    // build padded CSR in a single edge pass
    zero_kernel<<<(Nn + 255) / 256, 256>>>(deg, pool, cnt);
    fill_kernel<<<(Ee / 4 + 255) / 256, 256>>>(ei, deg, srcs);

    const float* cur = x;
    float* outs[Ll] = { x1, x2, x1 };
    for (int l = 0; l < Ll; l++) {
        gather_kernel<<<gather_blocks, 256>>>(cur, deg, srcs, agg);
        mlp_kernel<<<MLP_GRID, MLP_THREADS, MLP_SMEM>>>(
            agg,
            W1 + (size_t)l * 128 * 128, b1 + (size_t)l * 128,
            W2 + (size_t)l * 128 * 128, b2 + (size_t)l * 128,
            gamma + (size_t)l * 128, beta + (size_t)l * 128,
            rmean + (size_t)l * 128, rvar + (size_t)l * 128,
            outs[l]);
        cur = outs[l];
    }

    pool_kernel<<<pool_blocks, 256>>>(cur, batch, pool, cnt);
    final_kernel<<<1, 128>>>(pool, cnt, fc_w, fc_b, out);
}